// round 5
// baseline (speedup 1.0000x reference)
#include <cuda_runtime.h>
#include <cuda_bf16.h>
#include <cstdint>

#define BB 16
#define NN 256
#define DD 512
#define PE_ROWS 64        // pos = t - start < x[b,seg] <= 63 -> pos in [0,62]
#define ROW_BYTES (DD * 4) // 2048

__device__ __forceinline__ uint32_t smem_u32(const void* p) {
    uint32_t a;
    asm("{ .reg .u64 t; cvta.to.shared.u64 t, %1; cvt.u32.u64 %0, t; }"
        : "=r"(a) : "l"(p));
    return a;
}

__device__ __forceinline__ void bulk_s2g(void* gdst, uint32_t ssrc, int bytes) {
    asm volatile("cp.async.bulk.global.shared::cta.bulk_group [%0], [%1], %2;"
                 :: "l"(gdst), "r"(ssrc), "r"(bytes) : "memory");
}

// Single persistent kernel.
// Prologue: stage pos_enc rows 0..63 (128 KB) + per-batch cumsum (16 KB) +
// a 2 KB zero row into smem. Hot loop: ONE THREAD per output row — binary
// search + one 2 KB TMA bulk store (smem -> gmem). No registers in datapath.
__global__ __launch_bounds__(1024, 1)
void pe_gather_kernel(const int* __restrict__ x,
                      const float* __restrict__ pos_enc,
                      float* __restrict__ out, int T, int chunk) {
    extern __shared__ float smem[];
    float* s_pe   = smem;                               // PE_ROWS*DD floats (128 KB)
    int*   s_cum  = (int*)(smem + PE_ROWS * DD);        // BB*NN ints (16 KB)
    float* s_zero = (float*)(s_cum + BB * NN);          // DD floats (2 KB)

    const int warp = threadIdx.x >> 5;
    const int lane = threadIdx.x & 31;

    // ---- stage hot pos_enc rows ----
    {
        const float4* src = (const float4*)pos_enc;
        float4* dst = (float4*)s_pe;
        for (int i = threadIdx.x; i < PE_ROWS * DD / 4; i += blockDim.x)
            dst[i] = src[i];
    }
    // ---- zero row ----
    if (threadIdx.x < DD / 4)
        ((float4*)s_zero)[threadIdx.x] = make_float4(0.f, 0.f, 0.f, 0.f);

    // ---- per-CTA cumsum of x: warps 0..15 each scan one batch row ----
    if (warp < BB) {
        int carry = 0;
        for (int c = 0; c < NN / 32; c++) {
            int idx = c * 32 + lane;
            int v = x[warp * NN + idx];
            #pragma unroll
            for (int off = 1; off < 32; off <<= 1) {
                int n = __shfl_up_sync(0xffffffffu, v, off);
                if (lane >= off) v += n;
            }
            v += carry;
            s_cum[warp * NN + idx] = v;
            carry = __shfl_sync(0xffffffffu, v, 31);
        }
    }
    __syncthreads();
    // order generic smem writes before async-proxy (TMA) reads
    asm volatile("fence.proxy.async.shared::cta;" ::: "memory");

    const uint32_t s_pe_u   = smem_u32(s_pe);
    const uint32_t s_zero_u = smem_u32(s_zero);

    // ---- one thread per contiguous block of `chunk` rows (chunk==1 typ.) ----
    const long total = (long)BB * T;
    const long tg = (long)blockIdx.x * blockDim.x + threadIdx.x;
    long r0 = tg * chunk;
    bool issued = false;

    if (r0 < total) {
        long r1 = r0 + chunk; if (r1 > total) r1 = total;

        int b = (int)(r0 / T);
        int t = (int)(r0 - (long)b * T);
        const int* cum = s_cum + b * NN;
        int last = cum[NN - 1];

        // searchsorted(cum, t, 'right'): first seg with cum[seg] > t (257 answers -> 9 steps)
        int seg;
        {
            int lo = 0, hi = NN;
            #pragma unroll
            for (int it = 0; it < 9; it++) {
                if (lo < hi) {
                    int mid = (lo + hi) >> 1;
                    if (cum[mid] <= t) lo = mid + 1; else hi = mid;
                }
            }
            seg = lo;
        }

        for (long r = r0; r < r1; r++) {
            void* gdst = (void*)(out + r * (long)DD);
            if (t >= last) {
                bulk_s2g(gdst, s_zero_u, ROW_BYTES);
            } else {
                while (cum[seg] <= t) seg++;            // monotone advance
                const int start = (seg > 0) ? cum[seg - 1] : 0;
                const int pos = t - start;              // [0, 62]
                bulk_s2g(gdst, s_pe_u + pos * ROW_BYTES, ROW_BYTES);
            }
            issued = true;

            if (++t == T) {                              // batch-row boundary
                t = 0; b++;
                if (b < BB) { cum += NN; last = cum[NN - 1]; seg = 0; }
                else break;
            }
        }
    }

    // smem is immutable during the loop -> no intra-loop backpressure needed.
    if (issued) {
        asm volatile("cp.async.bulk.commit_group;" ::: "memory");
        asm volatile("cp.async.bulk.wait_group 0;" ::: "memory");
    }
}

extern "C" void kernel_launch(void* const* d_in, const int* in_sizes, int n_in,
                              void* d_out, int out_size) {
    const int*   x       = (const int*)d_in[0];
    const float* pos_enc = (const float*)d_in[1];
    float*       out     = (float*)d_out;

    const int T = out_size / (BB * DD);

    int sms = 148;
    cudaDeviceGetAttribute(&sms, cudaDevAttrMultiProcessorCount, 0);

    const long total = (long)BB * T;
    const long nthreads = (long)sms * 1024;
    const int chunk = (int)((total + nthreads - 1) / nthreads);

    const size_t smem_bytes = (size_t)(PE_ROWS * DD) * sizeof(float)
                            + (size_t)(BB * NN) * sizeof(int)
                            + (size_t)DD * sizeof(float);   // 149504 B
    cudaFuncSetAttribute(pe_gather_kernel,
                         cudaFuncAttributeMaxDynamicSharedMemorySize,
                         (int)smem_bytes);
    pe_gather_kernel<<<sms, 1024, smem_bytes>>>(x, pos_enc, out, T, chunk);
}

// round 6
// speedup vs baseline: 1.0485x; 1.0485x over previous
#include <cuda_runtime.h>
#include <cuda_bf16.h>

#define BB 16
#define NN 256
#define DD 512
#define PE_ROWS 64   // pos = t - start < x[b,seg] <= 63 -> pos in [0,62]

// Single persistent kernel.
// Prologue: stage pos_enc rows 0..63 (128 KB) + per-batch cumsum (16 KB) +
// 2 KB zero row in smem. Hot loop: each warp owns a contiguous row range and
// processes TWO rows per iteration (8 independent LDS.128 -> 8 STG.128.cs)
// for maximum outstanding-store MLP. Branchless: invalid rows read the zero row.
__global__ __launch_bounds__(1024, 1)
void pe_gather_kernel(const int* __restrict__ x,
                      const float* __restrict__ pos_enc,
                      float* __restrict__ out, int T, int chunk) {
    extern __shared__ float smem[];
    float* s_pe   = smem;                               // PE_ROWS*DD floats (128 KB)
    int*   s_cum  = (int*)(smem + PE_ROWS * DD);        // BB*NN ints (16 KB)
    float* s_zero = (float*)(s_cum + BB * NN);          // DD floats (2 KB)

    const int warp = threadIdx.x >> 5;
    const int lane = threadIdx.x & 31;

    // ---- stage hot pos_enc rows ----
    {
        const float4* src = (const float4*)pos_enc;
        float4* dst = (float4*)s_pe;
        for (int i = threadIdx.x; i < PE_ROWS * DD / 4; i += blockDim.x)
            dst[i] = src[i];
    }
    if (threadIdx.x < DD / 4)
        ((float4*)s_zero)[threadIdx.x] = make_float4(0.f, 0.f, 0.f, 0.f);

    // ---- per-CTA cumsum of x: warps 0..15 each scan one batch row ----
    if (warp < BB) {
        int carry = 0;
        for (int c = 0; c < NN / 32; c++) {
            int idx = c * 32 + lane;
            int v = x[warp * NN + idx];
            #pragma unroll
            for (int off = 1; off < 32; off <<= 1) {
                int n = __shfl_up_sync(0xffffffffu, v, off);
                if (lane >= off) v += n;
            }
            v += carry;
            s_cum[warp * NN + idx] = v;
            carry = __shfl_sync(0xffffffffu, v, 31);
        }
    }
    __syncthreads();

    // ---- contiguous row range for this warp ----
    const long total = (long)BB * T;
    const int warp_global = blockIdx.x * (blockDim.x >> 5) + warp;
    long r0 = (long)warp_global * chunk;
    if (r0 >= total) return;
    long r1 = r0 + chunk; if (r1 > total) r1 = total;

    int b = (int)(r0 / T);            // only division in the kernel
    int t = (int)(r0 - (long)b * T);
    const int* cum = s_cum + b * NN;
    int last = cum[NN - 1];

    // searchsorted(cum, t, 'right'): first seg with cum[seg] > t (257 answers -> 9 steps)
    int seg;
    {
        int lo = 0, hi = NN;
        #pragma unroll
        for (int it = 0; it < 9; it++) {
            if (lo < hi) {
                int mid = (lo + hi) >> 1;
                if (cum[mid] <= t) lo = mid + 1; else hi = mid;
            }
        }
        seg = lo;
    }

    long r = r0;
    while (r < r1) {
        const bool haveB = (r + 1 < r1);

        // ---- resolve source row A ----
        const float4* srcA = (const float4*)s_zero;
        if (t < last) {
            while (cum[seg] <= t) seg++;                 // monotone advance
            const int start = (seg > 0) ? cum[seg - 1] : 0;
            srcA = (const float4*)(s_pe + (t - start) * DD);
        }
        // advance state to row B
        if (++t == T) {
            t = 0; b++;
            if (b < BB) { cum += NN; last = cum[NN - 1]; seg = 0; }
            else last = 0;                               // loop will exit after this pair
        }

        // ---- resolve source row B ----
        const float4* srcB = (const float4*)s_zero;
        if (haveB) {
            if (t < last) {
                while (cum[seg] <= t) seg++;
                const int start = (seg > 0) ? cum[seg - 1] : 0;
                srcB = (const float4*)(s_pe + (t - start) * DD);
            }
            if (++t == T) {
                t = 0; b++;
                if (b < BB) { cum += NN; last = cum[NN - 1]; seg = 0; }
                else last = 0;
            }
        }

        // ---- 8 independent shared loads ----
        float4 a0 = srcA[lane +  0];
        float4 a1 = srcA[lane + 32];
        float4 a2 = srcA[lane + 64];
        float4 a3 = srcA[lane + 96];
        float4 b0, b1, b2, b3;
        if (haveB) {
            b0 = srcB[lane +  0];
            b1 = srcB[lane + 32];
            b2 = srcB[lane + 64];
            b3 = srcB[lane + 96];
        }

        // ---- 8 independent streaming stores ----
        float4* dstA = (float4*)(out + r * (long)DD);
        __stcs(dstA + lane +  0, a0);
        __stcs(dstA + lane + 32, a1);
        __stcs(dstA + lane + 64, a2);
        __stcs(dstA + lane + 96, a3);
        if (haveB) {
            float4* dstB = (float4*)(out + (r + 1) * (long)DD);
            __stcs(dstB + lane +  0, b0);
            __stcs(dstB + lane + 32, b1);
            __stcs(dstB + lane + 64, b2);
            __stcs(dstB + lane + 96, b3);
        }

        r += haveB ? 2 : 1;
        if (b >= BB) break;
    }
}

extern "C" void kernel_launch(void* const* d_in, const int* in_sizes, int n_in,
                              void* d_out, int out_size) {
    const int*   x       = (const int*)d_in[0];
    const float* pos_enc = (const float*)d_in[1];
    float*       out     = (float*)d_out;

    const int T = out_size / (BB * DD);

    int sms = 148;
    cudaDeviceGetAttribute(&sms, cudaDevAttrMultiProcessorCount, 0);

    const long total = (long)BB * T;
    const int nwarps = sms * 32;
    const int chunk = (int)((total + nwarps - 1) / nwarps);

    const size_t smem_bytes = (size_t)(PE_ROWS * DD) * sizeof(float)
                            + (size_t)(BB * NN) * sizeof(int)
                            + (size_t)DD * sizeof(float);   // 149504 B
    cudaFuncSetAttribute(pe_gather_kernel,
                         cudaFuncAttributeMaxDynamicSharedMemorySize,
                         (int)smem_bytes);
    pe_gather_kernel<<<sms, 1024, smem_bytes>>>(x, pos_enc, out, T, chunk);
}